// round 4
// baseline (speedup 1.0000x reference)
#include <cuda_runtime.h>
#include <cuda_bf16.h>
#include <math.h>
#include <stdint.h>

#define Bn   8
#define Nn   16384
#define Cn   128
#define OUTn 256
#define En   262144

// ---- scratch (static device globals; no allocation allowed) ----
__device__ __align__(16) int g_deg[Nn];
__device__ int   g_off[Nn + 1];
__device__ int   g_cur[Nn];
__device__ int   g_csr[En];
__device__ int   g_is64;
__device__ __nv_bfloat16 g_ahi[(size_t)Bn * Nn * Cn];   // 32 MB aggr hi
__device__ __nv_bfloat16 g_alo[(size_t)Bn * Nn * Cn];   // 32 MB aggr lo
__device__ __nv_bfloat16 g_wbh[(size_t)OUTn * Cn];      // W^T hi [N][K]
__device__ __nv_bfloat16 g_wbl[(size_t)OUTn * Cn];      // W^T lo [N][K]

// ============================================================
// Dtype detection: int64 vs int32 edge_index.
// ============================================================
__global__ void detect_kernel(const unsigned int* __restrict__ ei_raw) {
    int hi_zero = 0;
    for (int i = 0; i < 256; i++)
        if (ei_raw[2 * i + 1] == 0) hi_zero++;
    g_is64 = (hi_zero >= 250) ? 1 : 0;
}

__device__ __forceinline__ int load_idx(const void* ei, int pos, int is64) {
    if (is64) return (int)((const long long*)ei)[pos];
    return ((const int*)ei)[pos];
}

// ============================================================
// CSR build
// ============================================================
__global__ void init_kernel() {
    int i = blockIdx.x * blockDim.x + threadIdx.x;
    if (i < Nn) { g_deg[i] = 0; g_cur[i] = 0; }
}

__global__ void count_kernel(const void* __restrict__ ei) {
    int e = blockIdx.x * blockDim.x + threadIdx.x;
    int is64 = g_is64;
    if (e < En) {
        int r = load_idx(ei, e, is64);
        if ((unsigned)r < Nn) atomicAdd(&g_deg[r], 1);
    }
}

// shfl-based exclusive scan over 16384 ints: 1024 threads x 16 each
__global__ void __launch_bounds__(1024) scan_kernel() {
    __shared__ int wsum[32];
    int t = threadIdx.x, lane = t & 31, wid = t >> 5;
    int4 v0 = ((const int4*)g_deg)[t * 4 + 0];
    int4 v1 = ((const int4*)g_deg)[t * 4 + 1];
    int4 v2 = ((const int4*)g_deg)[t * 4 + 2];
    int4 v3 = ((const int4*)g_deg)[t * 4 + 3];
    int vals[16] = {v0.x, v0.y, v0.z, v0.w, v1.x, v1.y, v1.z, v1.w,
                    v2.x, v2.y, v2.z, v2.w, v3.x, v3.y, v3.z, v3.w};
    int tot = 0;
#pragma unroll
    for (int i = 0; i < 16; i++) tot += vals[i];
    int inc = tot;
#pragma unroll
    for (int off = 1; off < 32; off <<= 1) {
        int n = __shfl_up_sync(0xFFFFFFFFu, inc, off);
        if (lane >= off) inc += n;
    }
    if (lane == 31) wsum[wid] = inc;
    __syncthreads();
    if (wid == 0) {
        int w = wsum[lane];
        int wi = w;
#pragma unroll
        for (int off = 1; off < 32; off <<= 1) {
            int n = __shfl_up_sync(0xFFFFFFFFu, wi, off);
            if (lane >= off) wi += n;
        }
        wsum[lane] = wi - w;   // exclusive warp bases
    }
    __syncthreads();
    int run = wsum[wid] + (inc - tot);
#pragma unroll
    for (int i = 0; i < 16; i++) { g_off[t * 16 + i] = run; run += vals[i]; }
    if (t == 1023) g_off[Nn] = run;
}

__global__ void scatter_kernel(const void* __restrict__ ei) {
    int e = blockIdx.x * blockDim.x + threadIdx.x;
    int is64 = g_is64;
    if (e < En) {
        int r = load_idx(ei, e, is64);
        int c = load_idx(ei, En + e, is64);
        if ((unsigned)r < Nn && (unsigned)c < Nn) {
            int p = atomicAdd(&g_cur[r], 1);
            g_csr[g_off[r] + p] = c;
        }
    }
}

// ============================================================
// Aggregation: per node, all 8 batches, gather-max - x, bf16 hi/lo split
// ============================================================
__global__ void __launch_bounds__(128) aggregate_kernel(const float* __restrict__ x) {
    const int i = blockIdx.x;
    const int c = threadIdx.x;
    const int s = g_off[i];
    const int e = g_off[i + 1];

    float m[Bn];
#pragma unroll
    for (int b = 0; b < Bn; b++) m[b] = -INFINITY;

    int k = s;
    for (; k + 4 <= e; k += 4) {
        int j0 = g_csr[k + 0], j1 = g_csr[k + 1], j2 = g_csr[k + 2], j3 = g_csr[k + 3];
        size_t o0 = (size_t)j0 * Cn + c, o1 = (size_t)j1 * Cn + c;
        size_t o2 = (size_t)j2 * Cn + c, o3 = (size_t)j3 * Cn + c;
#pragma unroll
        for (int b = 0; b < Bn; b++) {
            size_t xb = (size_t)b * Nn * Cn;
            float v0 = __ldg(&x[xb + o0]);
            float v1 = __ldg(&x[xb + o1]);
            float v2 = __ldg(&x[xb + o2]);
            float v3 = __ldg(&x[xb + o3]);
            m[b] = fmaxf(m[b], fmaxf(fmaxf(v0, v1), fmaxf(v2, v3)));
        }
    }
    for (; k < e; k++) {
        int j = g_csr[k];
        size_t o = (size_t)j * Cn + c;
#pragma unroll
        for (int b = 0; b < Bn; b++)
            m[b] = fmaxf(m[b], __ldg(&x[(size_t)b * Nn * Cn + o]));
    }

    const bool none = (s == e);
    const size_t obase = (size_t)i * Cn + c;
#pragma unroll
    for (int b = 0; b < Bn; b++) {
        size_t idx = (size_t)b * Nn * Cn + obase;
        float v = (none ? 0.0f : m[b]) - x[idx];
        __nv_bfloat16 h = __float2bfloat16_rn(v);
        __nv_bfloat16 l = __float2bfloat16_rn(v - __bfloat162float(h));
        g_ahi[idx] = h;
        g_alo[idx] = l;
    }
}

// ============================================================
// W^T + bf16 hi/lo split:  W[K=128][N=256] -> Wt[N][K]
// ============================================================
__global__ void wt_split_kernel(const float* __restrict__ W) {
    int idx = blockIdx.x * blockDim.x + threadIdx.x;   // 32768
    int k = idx >> 8;
    int n = idx & 255;
    float a = W[idx];
    __nv_bfloat16 h = __float2bfloat16_rn(a);
    __nv_bfloat16 l = __float2bfloat16_rn(a - __bfloat162float(h));
    g_wbh[(size_t)n * Cn + k] = h;
    g_wbl[(size_t)n * Cn + k] = l;
}

// ============================================================
// GEMM via mma.sync bf16x3: (131072 x 128) @ (128 x 256) + bias + exact GELU
// CTA tile 128x64, 8 warps (warp tile 32x32), full-K SMEM tiles.
// ============================================================
#define MMA_BF16(d, a, b) \
    asm volatile("mma.sync.aligned.m16n8k16.row.col.f32.bf16.bf16.f32 " \
        "{%0,%1,%2,%3}, {%4,%5,%6,%7}, {%8,%9}, {%0,%1,%2,%3};" \
        : "+f"((d)[0]), "+f"((d)[1]), "+f"((d)[2]), "+f"((d)[3]) \
        : "r"((a)[0]), "r"((a)[1]), "r"((a)[2]), "r"((a)[3]), \
          "r"((b)[0]), "r"((b)[1]))

#define LDA 136            // 128 + 8 pad (bf16)
#define A_TILE_ELE (128 * LDA)
#define B_TILE_ELE (64 * LDA)
#define GEMM_SMEM ((2 * A_TILE_ELE + 2 * B_TILE_ELE) * 2)

__device__ __forceinline__ float gelu_exact(float v) {
    return 0.5f * v * (1.0f + erff(v * 0.70710678118654752f));
}

__global__ void __launch_bounds__(256, 2) gemm_mma_kernel(const float* __restrict__ bias,
                                                          float* __restrict__ out) {
    extern __shared__ __align__(16) __nv_bfloat16 smem[];
    __nv_bfloat16* Ah = smem;
    __nv_bfloat16* Al = smem + A_TILE_ELE;
    __nv_bfloat16* Bh = smem + 2 * A_TILE_ELE;
    __nv_bfloat16* Bl = smem + 2 * A_TILE_ELE + B_TILE_ELE;

    const int tid = threadIdx.x;
    const int wid = tid >> 5;
    const int lane = tid & 31;
    const size_t m0 = (size_t)blockIdx.x * 128;
    const int n0 = blockIdx.y * 64;
    const int warp_m = wid & 3;    // 4 x 32 rows
    const int warp_n = wid >> 2;   // 2 x 32 cols

    // ---- load A tiles (128 x 128 bf16, hi+lo) ----
#pragma unroll
    for (int it = 0; it < 8; it++) {
        int f4 = it * 256 + tid;          // 2048 float4-chunks of 8 bf16
        int r = f4 >> 4;
        int c8 = (f4 & 15) * 8;
        *(float4*)&Ah[r * LDA + c8] = *(const float4*)&g_ahi[(m0 + r) * Cn + c8];
        *(float4*)&Al[r * LDA + c8] = *(const float4*)&g_alo[(m0 + r) * Cn + c8];
    }
    // ---- load B tiles (64 n x 128 k bf16, hi+lo) ----
#pragma unroll
    for (int it = 0; it < 4; it++) {
        int f4 = it * 256 + tid;          // 1024
        int r = f4 >> 4;
        int c8 = (f4 & 15) * 8;
        *(float4*)&Bh[r * LDA + c8] = *(const float4*)&g_wbh[(size_t)(n0 + r) * Cn + c8];
        *(float4*)&Bl[r * LDA + c8] = *(const float4*)&g_wbl[(size_t)(n0 + r) * Cn + c8];
    }
    __syncthreads();

    const int gr = lane >> 2;       // group row 0..7
    const int tg = lane & 3;        // thread in group

    float acc[2][4][4];
#pragma unroll
    for (int mf = 0; mf < 2; mf++)
#pragma unroll
        for (int nf = 0; nf < 4; nf++)
#pragma unroll
            for (int q = 0; q < 4; q++) acc[mf][nf][q] = 0.0f;

#pragma unroll
    for (int kc = 0; kc < 8; kc++) {
        const int kb = kc * 16 + tg * 2;
        uint32_t ah[2][4], al[2][4], bh[4][2], bl[4][2];
#pragma unroll
        for (int mf = 0; mf < 2; mf++) {
            int m = warp_m * 32 + mf * 16 + gr;
            ah[mf][0] = *(const uint32_t*)&Ah[m * LDA + kb];
            ah[mf][1] = *(const uint32_t*)&Ah[(m + 8) * LDA + kb];
            ah[mf][2] = *(const uint32_t*)&Ah[m * LDA + kb + 8];
            ah[mf][3] = *(const uint32_t*)&Ah[(m + 8) * LDA + kb + 8];
            al[mf][0] = *(const uint32_t*)&Al[m * LDA + kb];
            al[mf][1] = *(const uint32_t*)&Al[(m + 8) * LDA + kb];
            al[mf][2] = *(const uint32_t*)&Al[m * LDA + kb + 8];
            al[mf][3] = *(const uint32_t*)&Al[(m + 8) * LDA + kb + 8];
        }
#pragma unroll
        for (int nf = 0; nf < 4; nf++) {
            int n = warp_n * 32 + nf * 8 + gr;
            bh[nf][0] = *(const uint32_t*)&Bh[n * LDA + kb];
            bh[nf][1] = *(const uint32_t*)&Bh[n * LDA + kb + 8];
            bl[nf][0] = *(const uint32_t*)&Bl[n * LDA + kb];
            bl[nf][1] = *(const uint32_t*)&Bl[n * LDA + kb + 8];
        }
#pragma unroll
        for (int mf = 0; mf < 2; mf++)
#pragma unroll
            for (int nf = 0; nf < 4; nf++) {
                MMA_BF16(acc[mf][nf], ah[mf], bh[nf]);
                MMA_BF16(acc[mf][nf], al[mf], bh[nf]);
                MMA_BF16(acc[mf][nf], ah[mf], bl[nf]);
            }
    }

    // ---- epilogue: bias + exact GELU, direct stores ----
#pragma unroll
    for (int nf = 0; nf < 4; nf++) {
        int col = n0 + warp_n * 32 + nf * 8 + tg * 2;
        float b0 = bias[col], b1 = bias[col + 1];
#pragma unroll
        for (int mf = 0; mf < 2; mf++) {
            size_t row = m0 + warp_m * 32 + mf * 16 + gr;
            float2 v0, v1;
            v0.x = gelu_exact(acc[mf][nf][0] + b0);
            v0.y = gelu_exact(acc[mf][nf][1] + b1);
            v1.x = gelu_exact(acc[mf][nf][2] + b0);
            v1.y = gelu_exact(acc[mf][nf][3] + b1);
            *(float2*)&out[row * OUTn + col]       = v0;
            *(float2*)&out[(row + 8) * OUTn + col] = v1;
        }
    }
}

// ============================================================
extern "C" void kernel_launch(void* const* d_in, const int* in_sizes, int n_in,
                              void* d_out, int out_size) {
    const float* x    = (const float*)d_in[0];
    const void*  ei   = d_in[1];
    const float* Wm   = (const float*)d_in[2];
    const float* bias = (const float*)d_in[3];
    float*       out  = (float*)d_out;

    cudaFuncSetAttribute(gemm_mma_kernel, cudaFuncAttributeMaxDynamicSharedMemorySize, GEMM_SMEM);

    detect_kernel<<<1, 1>>>((const unsigned int*)ei);
    init_kernel<<<(Nn + 255) / 256, 256>>>();
    count_kernel<<<En / 256, 256>>>(ei);
    scan_kernel<<<1, 1024>>>();
    scatter_kernel<<<En / 256, 256>>>(ei);
    wt_split_kernel<<<(Cn * OUTn) / 256, 256>>>(Wm);
    aggregate_kernel<<<Nn, 128>>>(x);
    dim3 g((Bn * Nn) / 128, OUTn / 64);
    gemm_mma_kernel<<<g, 256, GEMM_SMEM>>>(bias, out);
}

// round 5
// speedup vs baseline: 1.4546x; 1.4546x over previous
#include <cuda_runtime.h>
#include <cuda_bf16.h>
#include <math.h>
#include <stdint.h>

#define Bn   8
#define Nn   16384
#define Cn   128
#define OUTn 256
#define En   262144

// ---- scratch (static device globals; no allocation allowed) ----
__device__ __align__(16) int g_deg[Nn];
__device__ int   g_off[Nn + 1];
__device__ int   g_cur[Nn];
__device__ int   g_csr[En];
__device__ int   g_is64;
__device__ __nv_bfloat16 g_ahi[(size_t)Bn * Nn * Cn];   // 32 MB aggr hi
__device__ __nv_bfloat16 g_alo[(size_t)Bn * Nn * Cn];   // 32 MB aggr lo
__device__ __nv_bfloat16 g_wbh[(size_t)OUTn * Cn];      // W^T hi [N][K]
__device__ __nv_bfloat16 g_wbl[(size_t)OUTn * Cn];      // W^T lo [N][K]

// ============================================================
// Dtype detection: int64 vs int32 edge_index.
// ============================================================
__global__ void detect_kernel(const unsigned int* __restrict__ ei_raw) {
    int hi_zero = 0;
    for (int i = 0; i < 256; i++)
        if (ei_raw[2 * i + 1] == 0) hi_zero++;
    g_is64 = (hi_zero >= 250) ? 1 : 0;
}

__device__ __forceinline__ int load_idx(const void* ei, int pos, int is64) {
    if (is64) return (int)((const long long*)ei)[pos];
    return ((const int*)ei)[pos];
}

// ============================================================
// CSR build
// ============================================================
__global__ void init_kernel() {
    int i = blockIdx.x * blockDim.x + threadIdx.x;
    if (i < Nn) { g_deg[i] = 0; g_cur[i] = 0; }
}

__global__ void count_kernel(const void* __restrict__ ei) {
    int e = blockIdx.x * blockDim.x + threadIdx.x;
    int is64 = g_is64;
    if (e < En) {
        int r = load_idx(ei, e, is64);
        if ((unsigned)r < Nn) atomicAdd(&g_deg[r], 1);
    }
}

// shfl-based exclusive scan over 16384 ints
__global__ void __launch_bounds__(1024) scan_kernel() {
    __shared__ int wsum[32];
    int t = threadIdx.x, lane = t & 31, wid = t >> 5;
    int4 v0 = ((const int4*)g_deg)[t * 4 + 0];
    int4 v1 = ((const int4*)g_deg)[t * 4 + 1];
    int4 v2 = ((const int4*)g_deg)[t * 4 + 2];
    int4 v3 = ((const int4*)g_deg)[t * 4 + 3];
    int vals[16] = {v0.x, v0.y, v0.z, v0.w, v1.x, v1.y, v1.z, v1.w,
                    v2.x, v2.y, v2.z, v2.w, v3.x, v3.y, v3.z, v3.w};
    int tot = 0;
#pragma unroll
    for (int i = 0; i < 16; i++) tot += vals[i];
    int inc = tot;
#pragma unroll
    for (int off = 1; off < 32; off <<= 1) {
        int n = __shfl_up_sync(0xFFFFFFFFu, inc, off);
        if (lane >= off) inc += n;
    }
    if (lane == 31) wsum[wid] = inc;
    __syncthreads();
    if (wid == 0) {
        int w = wsum[lane];
        int wi = w;
#pragma unroll
        for (int off = 1; off < 32; off <<= 1) {
            int n = __shfl_up_sync(0xFFFFFFFFu, wi, off);
            if (lane >= off) wi += n;
        }
        wsum[lane] = wi - w;
    }
    __syncthreads();
    int run = wsum[wid] + (inc - tot);
#pragma unroll
    for (int i = 0; i < 16; i++) { g_off[t * 16 + i] = run; run += vals[i]; }
    if (t == 1023) g_off[Nn] = run;
}

__global__ void scatter_kernel(const void* __restrict__ ei) {
    int e = blockIdx.x * blockDim.x + threadIdx.x;
    int is64 = g_is64;
    if (e < En) {
        int r = load_idx(ei, e, is64);
        int c = load_idx(ei, En + e, is64);
        if ((unsigned)r < Nn && (unsigned)c < Nn) {
            int p = atomicAdd(&g_cur[r], 1);
            g_csr[g_off[r] + p] = c;
        }
    }
}

// ============================================================
// Aggregation: per node, all 8 batches, gather-max - x, bf16 hi/lo split
// ============================================================
__global__ void __launch_bounds__(128) aggregate_kernel(const float* __restrict__ x) {
    const int i = blockIdx.x;
    const int c = threadIdx.x;
    const int s = g_off[i];
    const int e = g_off[i + 1];

    float m[Bn];
#pragma unroll
    for (int b = 0; b < Bn; b++) m[b] = -INFINITY;

    int k = s;
    for (; k + 4 <= e; k += 4) {
        int j0 = g_csr[k + 0], j1 = g_csr[k + 1], j2 = g_csr[k + 2], j3 = g_csr[k + 3];
        size_t o0 = (size_t)j0 * Cn + c, o1 = (size_t)j1 * Cn + c;
        size_t o2 = (size_t)j2 * Cn + c, o3 = (size_t)j3 * Cn + c;
#pragma unroll
        for (int b = 0; b < Bn; b++) {
            size_t xb = (size_t)b * Nn * Cn;
            float v0 = __ldg(&x[xb + o0]);
            float v1 = __ldg(&x[xb + o1]);
            float v2 = __ldg(&x[xb + o2]);
            float v3 = __ldg(&x[xb + o3]);
            m[b] = fmaxf(m[b], fmaxf(fmaxf(v0, v1), fmaxf(v2, v3)));
        }
    }
    for (; k < e; k++) {
        int j = g_csr[k];
        size_t o = (size_t)j * Cn + c;
#pragma unroll
        for (int b = 0; b < Bn; b++)
            m[b] = fmaxf(m[b], __ldg(&x[(size_t)b * Nn * Cn + o]));
    }

    const bool none = (s == e);
    const size_t obase = (size_t)i * Cn + c;
#pragma unroll
    for (int b = 0; b < Bn; b++) {
        size_t idx = (size_t)b * Nn * Cn + obase;
        float v = (none ? 0.0f : m[b]) - x[idx];
        __nv_bfloat16 h = __float2bfloat16_rn(v);
        __nv_bfloat16 l = __float2bfloat16_rn(v - __bfloat162float(h));
        g_ahi[idx] = h;
        g_alo[idx] = l;
    }
}

// ============================================================
// W^T + bf16 hi/lo split:  W[K=128][N=256] -> Wt[N][K]
// ============================================================
__global__ void wt_split_kernel(const float* __restrict__ W) {
    int idx = blockIdx.x * blockDim.x + threadIdx.x;   // 32768
    int k = idx >> 8;
    int n = idx & 255;
    float a = W[idx];
    __nv_bfloat16 h = __float2bfloat16_rn(a);
    __nv_bfloat16 l = __float2bfloat16_rn(a - __bfloat162float(h));
    g_wbh[(size_t)n * Cn + k] = h;
    g_wbl[(size_t)n * Cn + k] = l;
}

// ============================================================
// GEMM via mma.sync bf16x3: (131072 x 128) @ (128 x 256) + bias + exact GELU
// CTA tile 128x256 (full N, A read once), 16 warps, warp tile 32x64.
// ============================================================
#define MMA_BF16(d, a, b) \
    asm volatile("mma.sync.aligned.m16n8k16.row.col.f32.bf16.bf16.f32 " \
        "{%0,%1,%2,%3}, {%4,%5,%6,%7}, {%8,%9}, {%0,%1,%2,%3};" \
        : "+f"((d)[0]), "+f"((d)[1]), "+f"((d)[2]), "+f"((d)[3]) \
        : "r"((a)[0]), "r"((a)[1]), "r"((a)[2]), "r"((a)[3]), \
          "r"((b)[0]), "r"((b)[1]))

#define LDA 136            // 128 + 8 pad (bf16)
#define A_TILE_ELE (128 * LDA)
#define B_TILE_ELE (256 * LDA)
#define GEMM_SMEM ((2 * A_TILE_ELE + 2 * B_TILE_ELE) * 2)

__device__ __forceinline__ float gelu_exact(float v) {
    return 0.5f * v * (1.0f + erff(v * 0.70710678118654752f));
}

__global__ void __launch_bounds__(512, 1) gemm_mma_kernel(const float* __restrict__ bias,
                                                          float* __restrict__ out) {
    extern __shared__ __align__(16) __nv_bfloat16 smem[];
    __nv_bfloat16* Ah = smem;
    __nv_bfloat16* Al = smem + A_TILE_ELE;
    __nv_bfloat16* Bh = smem + 2 * A_TILE_ELE;
    __nv_bfloat16* Bl = smem + 2 * A_TILE_ELE + B_TILE_ELE;

    const int tid = threadIdx.x;
    const int wid = tid >> 5;
    const int lane = tid & 31;
    const size_t m0 = (size_t)blockIdx.x * 128;
    const int warp_m = wid & 3;    // 4 x 32 rows
    const int warp_n = wid >> 2;   // 4 x 64 cols

    // ---- load A tiles (128 x 128 bf16, hi+lo): 2048 float4-chunks each ----
#pragma unroll
    for (int it = 0; it < 4; it++) {
        int f4 = it * 512 + tid;
        int r = f4 >> 4;
        int c8 = (f4 & 15) * 8;
        *(float4*)&Ah[r * LDA + c8] = *(const float4*)&g_ahi[(m0 + r) * Cn + c8];
        *(float4*)&Al[r * LDA + c8] = *(const float4*)&g_alo[(m0 + r) * Cn + c8];
    }
    // ---- load B tiles (256 n x 128 k bf16, hi+lo): 4096 float4-chunks each ----
#pragma unroll
    for (int it = 0; it < 8; it++) {
        int f4 = it * 512 + tid;
        int r = f4 >> 4;
        int c8 = (f4 & 15) * 8;
        *(float4*)&Bh[r * LDA + c8] = *(const float4*)&g_wbh[(size_t)r * Cn + c8];
        *(float4*)&Bl[r * LDA + c8] = *(const float4*)&g_wbl[(size_t)r * Cn + c8];
    }
    __syncthreads();

    const int gr = lane >> 2;       // group row 0..7
    const int tg = lane & 3;        // thread in group

    float acc[2][8][4];
#pragma unroll
    for (int mf = 0; mf < 2; mf++)
#pragma unroll
        for (int nf = 0; nf < 8; nf++)
#pragma unroll
            for (int q = 0; q < 4; q++) acc[mf][nf][q] = 0.0f;

#pragma unroll
    for (int kc = 0; kc < 8; kc++) {
        const int kb = kc * 16 + tg * 2;
        uint32_t ah[2][4], al[2][4];
#pragma unroll
        for (int mf = 0; mf < 2; mf++) {
            int m = warp_m * 32 + mf * 16 + gr;
            ah[mf][0] = *(const uint32_t*)&Ah[m * LDA + kb];
            ah[mf][1] = *(const uint32_t*)&Ah[(m + 8) * LDA + kb];
            ah[mf][2] = *(const uint32_t*)&Ah[m * LDA + kb + 8];
            ah[mf][3] = *(const uint32_t*)&Ah[(m + 8) * LDA + kb + 8];
            al[mf][0] = *(const uint32_t*)&Al[m * LDA + kb];
            al[mf][1] = *(const uint32_t*)&Al[(m + 8) * LDA + kb];
            al[mf][2] = *(const uint32_t*)&Al[m * LDA + kb + 8];
            al[mf][3] = *(const uint32_t*)&Al[(m + 8) * LDA + kb + 8];
        }
#pragma unroll
        for (int nf = 0; nf < 8; nf++) {
            int n = warp_n * 64 + nf * 8 + gr;
            uint32_t bh[2], bl[2];
            bh[0] = *(const uint32_t*)&Bh[n * LDA + kb];
            bh[1] = *(const uint32_t*)&Bh[n * LDA + kb + 8];
            bl[0] = *(const uint32_t*)&Bl[n * LDA + kb];
            bl[1] = *(const uint32_t*)&Bl[n * LDA + kb + 8];
#pragma unroll
            for (int mf = 0; mf < 2; mf++) {
                MMA_BF16(acc[mf][nf], ah[mf], bh);
                MMA_BF16(acc[mf][nf], al[mf], bh);
                MMA_BF16(acc[mf][nf], ah[mf], bl);
            }
        }
    }

    // ---- epilogue: bias + exact GELU, direct float2 stores ----
#pragma unroll
    for (int nf = 0; nf < 8; nf++) {
        int col = warp_n * 64 + nf * 8 + tg * 2;
        float b0 = __ldg(&bias[col]), b1 = __ldg(&bias[col + 1]);
#pragma unroll
        for (int mf = 0; mf < 2; mf++) {
            size_t row = m0 + warp_m * 32 + mf * 16 + gr;
            float2 v0, v1;
            v0.x = gelu_exact(acc[mf][nf][0] + b0);
            v0.y = gelu_exact(acc[mf][nf][1] + b1);
            v1.x = gelu_exact(acc[mf][nf][2] + b0);
            v1.y = gelu_exact(acc[mf][nf][3] + b1);
            *(float2*)&out[row * OUTn + col]       = v0;
            *(float2*)&out[(row + 8) * OUTn + col] = v1;
        }
    }
}

// ============================================================
extern "C" void kernel_launch(void* const* d_in, const int* in_sizes, int n_in,
                              void* d_out, int out_size) {
    const float* x    = (const float*)d_in[0];
    const void*  ei   = d_in[1];
    const float* Wm   = (const float*)d_in[2];
    const float* bias = (const float*)d_in[3];
    float*       out  = (float*)d_out;

    cudaFuncSetAttribute(gemm_mma_kernel, cudaFuncAttributeMaxDynamicSharedMemorySize, GEMM_SMEM);

    detect_kernel<<<1, 1>>>((const unsigned int*)ei);
    init_kernel<<<(Nn + 255) / 256, 256>>>();
    count_kernel<<<En / 256, 256>>>(ei);
    scan_kernel<<<1, 1024>>>();
    scatter_kernel<<<En / 256, 256>>>(ei);
    wt_split_kernel<<<(Cn * OUTn) / 256, 256>>>(Wm);
    aggregate_kernel<<<Nn, 128>>>(x);
    gemm_mma_kernel<<<(Bn * Nn) / 128, 512, GEMM_SMEM>>>(bias, out);
}

// round 6
// speedup vs baseline: 1.4885x; 1.0233x over previous
#include <cuda_runtime.h>
#include <cuda_bf16.h>
#include <math.h>
#include <stdint.h>

#define Bn   8
#define Nn   16384
#define Cn   128
#define OUTn 256
#define En   262144

// ---- scratch (static device globals; no allocation allowed) ----
__device__ __align__(16) int g_deg[Nn];
__device__ int   g_off[Nn + 1];
__device__ int   g_cur[Nn];
__device__ int   g_csr[En];
__device__ int   g_is64;
__device__ __nv_bfloat16 g_ahi[(size_t)Bn * Nn * Cn];   // 32 MB aggr hi
__device__ __nv_bfloat16 g_alo[(size_t)Bn * Nn * Cn];   // 32 MB aggr lo
__device__ __nv_bfloat16 g_wbh[(size_t)OUTn * Cn];      // W^T hi [N][K]
__device__ __nv_bfloat16 g_wbl[(size_t)OUTn * Cn];      // W^T lo [N][K]

__device__ __forceinline__ uint32_t smem_u32(const void* p) {
    return (uint32_t)__cvta_generic_to_shared(p);
}
#define CP_ASYNC16(dst_u32, src_ptr) \
    asm volatile("cp.async.cg.shared.global [%0], [%1], 16;" :: "r"(dst_u32), "l"(src_ptr))
#define CP_COMMIT() asm volatile("cp.async.commit_group;" ::: "memory")
#define CP_WAIT(n)  asm volatile("cp.async.wait_group %0;" :: "n"(n) : "memory")

// ============================================================
// detect dtype (int64 vs int32) + init degree arrays, one kernel
// ============================================================
__global__ void detinit_kernel(const unsigned int* __restrict__ ei_raw) {
    int i = blockIdx.x * blockDim.x + threadIdx.x;
    if (i < Nn) { g_deg[i] = 0; g_cur[i] = 0; }
    if (i == 0) {
        int hi_zero = 0;
        for (int k = 0; k < 256; k++)
            if (ei_raw[2 * k + 1] == 0) hi_zero++;
        g_is64 = (hi_zero >= 250) ? 1 : 0;
    }
}

__device__ __forceinline__ int load_idx(const void* ei, int pos, int is64) {
    if (is64) return (int)((const long long*)ei)[pos];
    return ((const int*)ei)[pos];
}

// ============================================================
// CSR build
// ============================================================
__global__ void count_kernel(const void* __restrict__ ei) {
    int e = blockIdx.x * blockDim.x + threadIdx.x;
    int is64 = g_is64;
    if (e < En) {
        int r = load_idx(ei, e, is64);
        if ((unsigned)r < Nn) atomicAdd(&g_deg[r], 1);
    }
}

// shfl-based exclusive scan over 16384 ints
__global__ void __launch_bounds__(1024) scan_kernel() {
    __shared__ int wsum[32];
    int t = threadIdx.x, lane = t & 31, wid = t >> 5;
    int4 v0 = ((const int4*)g_deg)[t * 4 + 0];
    int4 v1 = ((const int4*)g_deg)[t * 4 + 1];
    int4 v2 = ((const int4*)g_deg)[t * 4 + 2];
    int4 v3 = ((const int4*)g_deg)[t * 4 + 3];
    int vals[16] = {v0.x, v0.y, v0.z, v0.w, v1.x, v1.y, v1.z, v1.w,
                    v2.x, v2.y, v2.z, v2.w, v3.x, v3.y, v3.z, v3.w};
    int tot = 0;
#pragma unroll
    for (int i = 0; i < 16; i++) tot += vals[i];
    int inc = tot;
#pragma unroll
    for (int off = 1; off < 32; off <<= 1) {
        int n = __shfl_up_sync(0xFFFFFFFFu, inc, off);
        if (lane >= off) inc += n;
    }
    if (lane == 31) wsum[wid] = inc;
    __syncthreads();
    if (wid == 0) {
        int w = wsum[lane];
        int wi = w;
#pragma unroll
        for (int off = 1; off < 32; off <<= 1) {
            int n = __shfl_up_sync(0xFFFFFFFFu, wi, off);
            if (lane >= off) wi += n;
        }
        wsum[lane] = wi - w;
    }
    __syncthreads();
    int run = wsum[wid] + (inc - tot);
#pragma unroll
    for (int i = 0; i < 16; i++) { g_off[t * 16 + i] = run; run += vals[i]; }
    if (t == 1023) g_off[Nn] = run;
}

__global__ void scatter_kernel(const void* __restrict__ ei) {
    int e = blockIdx.x * blockDim.x + threadIdx.x;
    int is64 = g_is64;
    if (e < En) {
        int r = load_idx(ei, e, is64);
        int c = load_idx(ei, En + e, is64);
        if ((unsigned)r < Nn && (unsigned)c < Nn) {
            int p = atomicAdd(&g_cur[r], 1);
            g_csr[g_off[r] + p] = c;
        }
    }
}

// ============================================================
// Aggregation: per node, all 8 batches, gather-max - x, bf16 hi/lo split
// ============================================================
__global__ void __launch_bounds__(128) aggregate_kernel(const float* __restrict__ x) {
    const int i = blockIdx.x;
    const int c = threadIdx.x;
    const int s = g_off[i];
    const int e = g_off[i + 1];

    float m[Bn];
#pragma unroll
    for (int b = 0; b < Bn; b++) m[b] = -INFINITY;

    int k = s;
    for (; k + 4 <= e; k += 4) {
        int j0 = g_csr[k + 0], j1 = g_csr[k + 1], j2 = g_csr[k + 2], j3 = g_csr[k + 3];
        size_t o0 = (size_t)j0 * Cn + c, o1 = (size_t)j1 * Cn + c;
        size_t o2 = (size_t)j2 * Cn + c, o3 = (size_t)j3 * Cn + c;
#pragma unroll
        for (int b = 0; b < Bn; b++) {
            size_t xb = (size_t)b * Nn * Cn;
            float v0 = __ldg(&x[xb + o0]);
            float v1 = __ldg(&x[xb + o1]);
            float v2 = __ldg(&x[xb + o2]);
            float v3 = __ldg(&x[xb + o3]);
            m[b] = fmaxf(m[b], fmaxf(fmaxf(v0, v1), fmaxf(v2, v3)));
        }
    }
    for (; k < e; k++) {
        int j = g_csr[k];
        size_t o = (size_t)j * Cn + c;
#pragma unroll
        for (int b = 0; b < Bn; b++)
            m[b] = fmaxf(m[b], __ldg(&x[(size_t)b * Nn * Cn + o]));
    }

    const bool none = (s == e);
    const size_t obase = (size_t)i * Cn + c;
#pragma unroll
    for (int b = 0; b < Bn; b++) {
        size_t idx = (size_t)b * Nn * Cn + obase;
        float v = (none ? 0.0f : m[b]) - x[idx];
        __nv_bfloat16 h = __float2bfloat16_rn(v);
        __nv_bfloat16 l = __float2bfloat16_rn(v - __bfloat162float(h));
        g_ahi[idx] = h;
        g_alo[idx] = l;
    }
}

// ============================================================
// W^T + bf16 hi/lo split:  W[K=128][N=256] -> Wt[N][K]
// ============================================================
__global__ void wt_split_kernel(const float* __restrict__ W) {
    int idx = blockIdx.x * blockDim.x + threadIdx.x;   // 32768
    int k = idx >> 8;
    int n = idx & 255;
    float a = W[idx];
    __nv_bfloat16 h = __float2bfloat16_rn(a);
    __nv_bfloat16 l = __float2bfloat16_rn(a - __bfloat162float(h));
    g_wbh[(size_t)n * Cn + k] = h;
    g_wbl[(size_t)n * Cn + k] = l;
}

// ============================================================
// GEMM via mma.sync bf16x3: (131072 x 128) @ (128 x 256) + bias + exact GELU
// CTA tile 128x256, 16 warps, warp tile 32x64.
// 2-stage cp.async pipeline over K halves (64 each).
// ============================================================
#define MMA_BF16(d, a, b) \
    asm volatile("mma.sync.aligned.m16n8k16.row.col.f32.bf16.bf16.f32 " \
        "{%0,%1,%2,%3}, {%4,%5,%6,%7}, {%8,%9}, {%0,%1,%2,%3};" \
        : "+f"((d)[0]), "+f"((d)[1]), "+f"((d)[2]), "+f"((d)[3]) \
        : "r"((a)[0]), "r"((a)[1]), "r"((a)[2]), "r"((a)[3]), \
          "r"((b)[0]), "r"((b)[1]))

#define LDK   72                      // 64 + 8 pad (bf16)
#define A_ST  (128 * LDK)             // elements per (stage, part) = 9216
#define B_ST  (256 * LDK)             // 18432
#define OFF_AH 0
#define OFF_AL (2 * A_ST)
#define OFF_BH (4 * A_ST)
#define OFF_BL (4 * A_ST + 2 * B_ST)
#define GEMM_SMEM ((4 * A_ST + 4 * B_ST) * 2)   // 221184 bytes

__device__ __forceinline__ float gelu_exact(float v) {
    return 0.5f * v * (1.0f + erff(v * 0.70710678118654752f));
}

__global__ void __launch_bounds__(512, 1) gemm_mma_kernel(const float* __restrict__ bias,
                                                          float* __restrict__ out) {
    extern __shared__ __align__(16) __nv_bfloat16 smem[];
    const int tid = threadIdx.x;
    const int wid = tid >> 5;
    const int lane = tid & 31;
    const size_t m0 = (size_t)blockIdx.x * 128;
    const int warp_m = wid & 3;    // 4 x 32 rows
    const int warp_n = wid >> 2;   // 4 x 64 cols

    // ---- async load both K-stages ----
#pragma unroll
    for (int s = 0; s < 2; s++) {
        const int ks = s * 64;
        // A hi/lo: 1024 16B-chunks each
#pragma unroll
        for (int it = 0; it < 2; it++) {
            int q = it * 512 + tid;
            int r = q >> 3;
            int c8 = (q & 7) * 8;
            uint32_t dh = smem_u32(&smem[OFF_AH + s * A_ST + r * LDK + c8]);
            uint32_t dl = smem_u32(&smem[OFF_AL + s * A_ST + r * LDK + c8]);
            CP_ASYNC16(dh, &g_ahi[(m0 + r) * Cn + ks + c8]);
            CP_ASYNC16(dl, &g_alo[(m0 + r) * Cn + ks + c8]);
        }
        // B hi/lo: 2048 16B-chunks each
#pragma unroll
        for (int it = 0; it < 4; it++) {
            int q = it * 512 + tid;
            int n = q >> 3;
            int c8 = (q & 7) * 8;
            uint32_t dh = smem_u32(&smem[OFF_BH + s * B_ST + n * LDK + c8]);
            uint32_t dl = smem_u32(&smem[OFF_BL + s * B_ST + n * LDK + c8]);
            CP_ASYNC16(dh, &g_wbh[(size_t)n * Cn + ks + c8]);
            CP_ASYNC16(dl, &g_wbl[(size_t)n * Cn + ks + c8]);
        }
        CP_COMMIT();
    }

    const int gr = lane >> 2;       // group row 0..7
    const int tg = lane & 3;        // thread in group

    float acc[2][8][4];
#pragma unroll
    for (int mf = 0; mf < 2; mf++)
#pragma unroll
        for (int nf = 0; nf < 8; nf++)
#pragma unroll
            for (int q = 0; q < 4; q++) acc[mf][nf][q] = 0.0f;

#pragma unroll
    for (int s = 0; s < 2; s++) {
        if (s == 0) { CP_WAIT(1); } else { CP_WAIT(0); }
        __syncthreads();
        const __nv_bfloat16* Ah = smem + OFF_AH + s * A_ST;
        const __nv_bfloat16* Al = smem + OFF_AL + s * A_ST;
        const __nv_bfloat16* Bh = smem + OFF_BH + s * B_ST;
        const __nv_bfloat16* Bl = smem + OFF_BL + s * B_ST;

#pragma unroll
        for (int kc = 0; kc < 4; kc++) {
            const int kb = kc * 16 + tg * 2;
            uint32_t ah[2][4], al[2][4];
#pragma unroll
            for (int mf = 0; mf < 2; mf++) {
                int m = warp_m * 32 + mf * 16 + gr;
                ah[mf][0] = *(const uint32_t*)&Ah[m * LDK + kb];
                ah[mf][1] = *(const uint32_t*)&Ah[(m + 8) * LDK + kb];
                ah[mf][2] = *(const uint32_t*)&Ah[m * LDK + kb + 8];
                ah[mf][3] = *(const uint32_t*)&Ah[(m + 8) * LDK + kb + 8];
                al[mf][0] = *(const uint32_t*)&Al[m * LDK + kb];
                al[mf][1] = *(const uint32_t*)&Al[(m + 8) * LDK + kb];
                al[mf][2] = *(const uint32_t*)&Al[m * LDK + kb + 8];
                al[mf][3] = *(const uint32_t*)&Al[(m + 8) * LDK + kb + 8];
            }
#pragma unroll
            for (int nf = 0; nf < 8; nf++) {
                int n = warp_n * 64 + nf * 8 + gr;
                uint32_t bh[2], bl[2];
                bh[0] = *(const uint32_t*)&Bh[n * LDK + kb];
                bh[1] = *(const uint32_t*)&Bh[n * LDK + kb + 8];
                bl[0] = *(const uint32_t*)&Bl[n * LDK + kb];
                bl[1] = *(const uint32_t*)&Bl[n * LDK + kb + 8];
#pragma unroll
                for (int mf = 0; mf < 2; mf++) {
                    MMA_BF16(acc[mf][nf], ah[mf], bh);
                    MMA_BF16(acc[mf][nf], al[mf], bh);
                    MMA_BF16(acc[mf][nf], ah[mf], bl);
                }
            }
        }
        if (s == 0) __syncthreads();   // stage0 regions not reused; sync only for order
    }

    // ---- epilogue: bias + exact GELU, direct float2 stores ----
#pragma unroll
    for (int nf = 0; nf < 8; nf++) {
        int col = warp_n * 64 + nf * 8 + tg * 2;
        float b0 = __ldg(&bias[col]), b1 = __ldg(&bias[col + 1]);
#pragma unroll
        for (int mf = 0; mf < 2; mf++) {
            size_t row = m0 + warp_m * 32 + mf * 16 + gr;
            float2 v0, v1;
            v0.x = gelu_exact(acc[mf][nf][0] + b0);
            v0.y = gelu_exact(acc[mf][nf][1] + b1);
            v1.x = gelu_exact(acc[mf][nf][2] + b0);
            v1.y = gelu_exact(acc[mf][nf][3] + b1);
            *(float2*)&out[row * OUTn + col]       = v0;
            *(float2*)&out[(row + 8) * OUTn + col] = v1;
        }
    }
}

// ============================================================
extern "C" void kernel_launch(void* const* d_in, const int* in_sizes, int n_in,
                              void* d_out, int out_size) {
    const float* x    = (const float*)d_in[0];
    const void*  ei   = d_in[1];
    const float* Wm   = (const float*)d_in[2];
    const float* bias = (const float*)d_in[3];
    float*       out  = (float*)d_out;

    cudaFuncSetAttribute(gemm_mma_kernel, cudaFuncAttributeMaxDynamicSharedMemorySize, GEMM_SMEM);

    detinit_kernel<<<(Nn + 255) / 256, 256>>>((const unsigned int*)ei);
    count_kernel<<<En / 256, 256>>>(ei);
    scan_kernel<<<1, 1024>>>();
    scatter_kernel<<<En / 256, 256>>>(ei);
    wt_split_kernel<<<(Cn * OUTn) / 256, 256>>>(Wm);
    aggregate_kernel<<<Nn, 128>>>(x);
    gemm_mma_kernel<<<(Bn * Nn) / 128, 512, GEMM_SMEM>>>(bias, out);
}